// round 14
// baseline (speedup 1.0000x reference)
#include <cuda_runtime.h>
#include <cstdint>

#define BATCH    64
#define LSEQ     16384
#define FCH      128
#define KW       16
#define OUT_LEN  16369            // (16384 - 16) + 1
#define TILE_O   128              // o per block (2 og-groups x 4 subtiles of 16)
#define NTHREADS 256              // 8 warps: og = wid>>2 (0..1), fg = wid&3
#define XWIN     (TILE_O + KW - 1)  // 143

// split v into tf32 hi + tf32 lo (3xTF32 emulation parts)
__device__ __forceinline__ void split_tf32(float v, uint32_t& hi, uint32_t& lo) {
    uint32_t h;
    asm("cvt.rna.tf32.f32 %0, %1;" : "=r"(h) : "f"(v));
    float rem = v - __uint_as_float(h);      // tf32 bits are valid fp32
    uint32_t l;
    asm("cvt.rna.tf32.f32 %0, %1;" : "=r"(l) : "f"(rem));
    hi = h; lo = l;
}

// D(16x8) += A(16x8) * B(8x8)^T  -- tf32 inputs, fp32 accumulate
__device__ __forceinline__ void mma_16n8k8(float c[4], const uint32_t a[4],
                                           const uint32_t b[2]) {
    asm volatile(
        "mma.sync.aligned.m16n8k8.row.col.f32.tf32.tf32.f32 "
        "{%0,%1,%2,%3}, {%4,%5,%6,%7}, {%8,%9}, {%0,%1,%2,%3};"
        : "+f"(c[0]), "+f"(c[1]), "+f"(c[2]), "+f"(c[3])
        : "r"(a[0]), "r"(a[1]), "r"(a[2]), "r"(a[3]), "r"(b[0]), "r"(b[1]));
}

__device__ __forceinline__ float relu_(float v) { return fmaxf(v, 0.0f); }

__global__ __launch_bounds__(NTHREADS, 3)   // regs currently 78; cap 85 = slack
void speccnn1d_mma_kernel(const float* __restrict__ x,
                          const float* __restrict__ kern,
                          float* __restrict__ out) {
    __shared__ uint32_t xs_hi[XWIN];
    __shared__ uint32_t xs_lo[XWIN];

    const int tid  = threadIdx.x;
    const int lane = tid & 31;
    const int wid  = tid >> 5;
    const int b    = blockIdx.y;
    const int o0   = blockIdx.x * TILE_O;

    // ---- stage x window, pre-split into tf32 hi/lo (once per CTA) ----
    if (tid < XWIN) {
        int xi = o0 + tid;
        float v = (xi < LSEQ) ? __ldg(&x[(size_t)b * LSEQ + xi]) : 0.0f;
        uint32_t h, l;
        split_tf32(v, h, l);
        xs_hi[tid] = h;
        xs_lo[tid] = l;
    }
    __syncthreads();

    const int fg = wid & 3;                  // f-group: 32 channels
    const int og = wid >> 2;                 // o-group: 64 rows (4 subtiles)
    const int t  = lane & 3;                 // threadID in group
    const int g  = lane >> 2;                // groupID

    // ---- B fragments (weights), 3xTF32 split, PERMUTED f layout ----
    // Block nb, fragment-col j holds logical f = fg*32 + 8*(j>>1) + 2*nb + (j&1).
    // (col index within an nb block equals g for the B fragment rows.)
    // => thread t's C cols across nb form contiguous f = fg*32 + 8t .. 8t+7.
    uint32_t Bb[4][2][2], Bs[4][2][2];
    #pragma unroll
    for (int nb = 0; nb < 4; nb++) {
        const int frow = fg * 32 + 8 * (g >> 1) + 2 * nb + (g & 1);
        const float* wr = kern + (size_t)frow * KW;
        #pragma unroll
        for (int k = 0; k < 2; k++) {
            split_tf32(__ldg(&wr[k * 8 + t]),     Bb[nb][k][0], Bs[nb][k][0]);
            split_tf32(__ldg(&wr[k * 8 + t + 4]), Bb[nb][k][1], Bs[nb][k][1]);
        }
    }

    // ---- 4 o-subtiles of 16 per warp ----
    #pragma unroll
    for (int sub = 0; sub < 4; sub++) {
        const int obase = og * 64 + sub * 16;      // local o of this subtile

        float C[4][4];
        #pragma unroll
        for (int nb = 0; nb < 4; nb++)
            #pragma unroll
            for (int j = 0; j < 4; j++) C[nb][j] = 0.0f;

        #pragma unroll
        for (int k = 0; k < 2; k++) {
            const int base = obase + g;
            const int kc   = k * 8 + t;
            uint32_t Ab[4], Al[4];
            Ab[0] = xs_hi[base + kc];          Al[0] = xs_lo[base + kc];
            Ab[1] = xs_hi[base + 8 + kc];      Al[1] = xs_lo[base + 8 + kc];
            Ab[2] = xs_hi[base + kc + 4];      Al[2] = xs_lo[base + kc + 4];
            Ab[3] = xs_hi[base + 8 + kc + 4];  Al[3] = xs_lo[base + 8 + kc + 4];

            #pragma unroll
            for (int nb = 0; nb < 4; nb++) {
                mma_16n8k8(C[nb], Ab, Bb[nb][k]);   // big * big
                mma_16n8k8(C[nb], Ab, Bs[nb][k]);   // big * small
                mma_16n8k8(C[nb], Al, Bb[nb][k]);   // small * big
            }
        }

        // ---- epilogue: relu + 2x STG.128 per row ----
        // Thread t's channels: f = fg*32 + 8t + {0..7}; rows g and g+8.
        const int r0 = o0 + obase + g;
        float* orow = out + ((size_t)b * OUT_LEN + r0) * FCH + fg * 32 + 8 * t;

        if (r0 < OUT_LEN) {
            float4 v0, v1;
            v0.x = relu_(C[0][0]); v0.y = relu_(C[0][1]);
            v0.z = relu_(C[1][0]); v0.w = relu_(C[1][1]);
            v1.x = relu_(C[2][0]); v1.y = relu_(C[2][1]);
            v1.z = relu_(C[3][0]); v1.w = relu_(C[3][1]);
            *reinterpret_cast<float4*>(orow)     = v0;
            *reinterpret_cast<float4*>(orow + 4) = v1;
        }
        if (r0 + 8 < OUT_LEN) {
            float* orow2 = orow + (size_t)8 * FCH;
            float4 v0, v1;
            v0.x = relu_(C[0][2]); v0.y = relu_(C[0][3]);
            v0.z = relu_(C[1][2]); v0.w = relu_(C[1][3]);
            v1.x = relu_(C[2][2]); v1.y = relu_(C[2][3]);
            v1.z = relu_(C[3][2]); v1.w = relu_(C[3][3]);
            *reinterpret_cast<float4*>(orow2)     = v0;
            *reinterpret_cast<float4*>(orow2 + 4) = v1;
        }
    }
}

extern "C" void kernel_launch(void* const* d_in, const int* in_sizes, int n_in,
                              void* d_out, int out_size) {
    const float* x    = (const float*)d_in[0];   // (64, 16384) fp32
    const float* kern = (const float*)d_in[1];   // (128, 16)  fp32
    float* out        = (float*)d_out;           // (64, 16369, 128) fp32

    dim3 grid((OUT_LEN + TILE_O - 1) / TILE_O, BATCH);   // (128, 64)
    speccnn1d_mma_kernel<<<grid, NTHREADS>>>(x, kern, out);
}

// round 15
// speedup vs baseline: 1.4530x; 1.4530x over previous
#include <cuda_runtime.h>
#include <cstdint>

#define BATCH    64
#define LSEQ     16384
#define FCH      128
#define KW       16
#define OUT_LEN  16369            // (16384 - 16) + 1
#define TILE_O   128              // o per block (2 og-groups x 4 subtiles of 16)
#define NTHREADS 256              // 8 warps: og = wid>>2 (0..1), fg = wid&3
#define XWIN     (TILE_O + KW - 1)  // 143

// split v into tf32 hi + tf32 lo (3xTF32 emulation parts)
__device__ __forceinline__ void split_tf32(float v, uint32_t& hi, uint32_t& lo) {
    uint32_t h;
    asm("cvt.rna.tf32.f32 %0, %1;" : "=r"(h) : "f"(v));
    float rem = v - __uint_as_float(h);      // tf32 bits are valid fp32
    uint32_t l;
    asm("cvt.rna.tf32.f32 %0, %1;" : "=r"(l) : "f"(rem));
    hi = h; lo = l;
}

// D(16x8) += A(16x8) * B(8x8)^T  -- tf32 inputs, fp32 accumulate
__device__ __forceinline__ void mma_16n8k8(float c[4], const uint32_t a[4],
                                           const uint32_t b[2]) {
    asm volatile(
        "mma.sync.aligned.m16n8k8.row.col.f32.tf32.tf32.f32 "
        "{%0,%1,%2,%3}, {%4,%5,%6,%7}, {%8,%9}, {%0,%1,%2,%3};"
        : "+f"(c[0]), "+f"(c[1]), "+f"(c[2]), "+f"(c[3])
        : "r"(a[0]), "r"(a[1]), "r"(a[2]), "r"(a[3]), "r"(b[0]), "r"(b[1]));
}

__device__ __forceinline__ float relu_(float v) { return fmaxf(v, 0.0f); }

__global__ __launch_bounds__(NTHREADS, 2)   // regs ~78 -> 3 CTAs resident anyway
void speccnn1d_mma_kernel(const float* __restrict__ x,
                          const float* __restrict__ kern,
                          float* __restrict__ out) {
    __shared__ uint32_t xs_hi[XWIN];
    __shared__ uint32_t xs_lo[XWIN];

    const int tid  = threadIdx.x;
    const int lane = tid & 31;
    const int wid  = tid >> 5;
    const int b    = blockIdx.y;
    const int o0   = blockIdx.x * TILE_O;

    // ---- stage x window, pre-split into tf32 hi/lo (once per CTA) ----
    if (tid < XWIN) {
        int xi = o0 + tid;
        float v = (xi < LSEQ) ? __ldg(&x[(size_t)b * LSEQ + xi]) : 0.0f;
        uint32_t h, l;
        split_tf32(v, h, l);
        xs_hi[tid] = h;
        xs_lo[tid] = l;
    }
    __syncthreads();

    const int fg = wid & 3;                  // f-group: 32 channels
    const int og = wid >> 2;                 // o-group: 64 rows (4 subtiles)
    const int t  = lane & 3;                 // threadID in group
    const int g  = lane >> 2;                // groupID

    // ---- B fragments, 3xTF32 split, sector-contiguous f permutation ----
    // Block nb, fragment n-index n holds logical
    //   f = fg*32 + 16*(nb>>1) + 4*(n>>1) + 2*(nb&1) + (n&1)   (bijective)
    // => thread t's C cols: nb=0: 4t,4t+1; nb=1: 4t+2,4t+3;
    //                       nb=2: 16+4t,16+4t+1; nb=3: 16+4t+2,16+4t+3.
    // => two float4 stores at f = fg*32+4t and fg*32+16+4t; quad t=0..3 covers
    //    64B contiguous per STG.128 (full sectors, full lines).
    uint32_t Bb[4][2][2], Bs[4][2][2];
    #pragma unroll
    for (int nb = 0; nb < 4; nb++) {
        const int frow = fg * 32 + 16 * (nb >> 1) + 4 * (g >> 1)
                       + 2 * (nb & 1) + (g & 1);
        const float* wr = kern + (size_t)frow * KW;
        #pragma unroll
        for (int k = 0; k < 2; k++) {
            split_tf32(__ldg(&wr[k * 8 + t]),     Bb[nb][k][0], Bs[nb][k][0]);
            split_tf32(__ldg(&wr[k * 8 + t + 4]), Bb[nb][k][1], Bs[nb][k][1]);
        }
    }

    // ---- 4 o-subtiles of 16 per warp ----
    #pragma unroll
    for (int sub = 0; sub < 4; sub++) {
        const int obase = og * 64 + sub * 16;      // local o of this subtile

        float C[4][4];
        #pragma unroll
        for (int nb = 0; nb < 4; nb++)
            #pragma unroll
            for (int j = 0; j < 4; j++) C[nb][j] = 0.0f;

        #pragma unroll
        for (int k = 0; k < 2; k++) {
            const int base = obase + g;
            const int kc   = k * 8 + t;
            uint32_t Ab[4], Al[4];
            Ab[0] = xs_hi[base + kc];          Al[0] = xs_lo[base + kc];
            Ab[1] = xs_hi[base + 8 + kc];      Al[1] = xs_lo[base + 8 + kc];
            Ab[2] = xs_hi[base + kc + 4];      Al[2] = xs_lo[base + kc + 4];
            Ab[3] = xs_hi[base + 8 + kc + 4];  Al[3] = xs_lo[base + 8 + kc + 4];

            #pragma unroll
            for (int nb = 0; nb < 4; nb++) {
                mma_16n8k8(C[nb], Ab, Bb[nb][k]);   // big * big
                mma_16n8k8(C[nb], Ab, Bs[nb][k]);   // big * small
                mma_16n8k8(C[nb], Al, Bb[nb][k]);   // small * big
            }
        }

        // ---- epilogue: relu + 2x sector-contiguous STG.128 per row ----
        const int r0 = o0 + obase + g;
        float* orow = out + ((size_t)b * OUT_LEN + r0) * FCH + fg * 32;

        if (r0 < OUT_LEN) {
            float4 v0, v1;
            v0.x = relu_(C[0][0]); v0.y = relu_(C[0][1]);
            v0.z = relu_(C[1][0]); v0.w = relu_(C[1][1]);
            v1.x = relu_(C[2][0]); v1.y = relu_(C[2][1]);
            v1.z = relu_(C[3][0]); v1.w = relu_(C[3][1]);
            *reinterpret_cast<float4*>(orow + 4 * t)      = v0;   // f = 4t..4t+3
            *reinterpret_cast<float4*>(orow + 16 + 4 * t) = v1;   // f = 16+4t..
        }
        if (r0 + 8 < OUT_LEN) {
            float* orow2 = orow + (size_t)8 * FCH;
            float4 v0, v1;
            v0.x = relu_(C[0][2]); v0.y = relu_(C[0][3]);
            v0.z = relu_(C[1][2]); v0.w = relu_(C[1][3]);
            v1.x = relu_(C[2][2]); v1.y = relu_(C[2][3]);
            v1.z = relu_(C[3][2]); v1.w = relu_(C[3][3]);
            *reinterpret_cast<float4*>(orow2 + 4 * t)      = v0;
            *reinterpret_cast<float4*>(orow2 + 16 + 4 * t) = v1;
        }
    }
}

extern "C" void kernel_launch(void* const* d_in, const int* in_sizes, int n_in,
                              void* d_out, int out_size) {
    const float* x    = (const float*)d_in[0];   // (64, 16384) fp32
    const float* kern = (const float*)d_in[1];   // (128, 16)  fp32
    float* out        = (float*)d_out;           // (64, 16369, 128) fp32

    dim3 grid((OUT_LEN + TILE_O - 1) / TILE_O, BATCH);   // (128, 64)
    speccnn1d_mma_kernel<<<grid, NTHREADS>>>(x, kern, out);
}

// round 16
// speedup vs baseline: 1.5855x; 1.0912x over previous
#include <cuda_runtime.h>
#include <cstdint>

#define BATCH    64
#define LSEQ     16384
#define FCH      128
#define KW       16
#define OUT_LEN  16369            // (16384 - 16) + 1
#define TILE_O   256              // o per block (2 og-groups x 8 subtiles of 16)
#define NTHREADS 256              // 8 warps: og = wid>>2 (0..1), fg = wid&3
#define NSUB     8                // subtiles per warp
#define XWIN     (TILE_O + KW - 1)  // 271

// split v into tf32 hi + tf32 lo (3xTF32 emulation parts)
__device__ __forceinline__ void split_tf32(float v, uint32_t& hi, uint32_t& lo) {
    uint32_t h;
    asm("cvt.rna.tf32.f32 %0, %1;" : "=r"(h) : "f"(v));
    float rem = v - __uint_as_float(h);      // tf32 bits are valid fp32
    uint32_t l;
    asm("cvt.rna.tf32.f32 %0, %1;" : "=r"(l) : "f"(rem));
    hi = h; lo = l;
}

// D(16x8) += A(16x8) * B(8x8)^T  -- tf32 inputs, fp32 accumulate
__device__ __forceinline__ void mma_16n8k8(float c[4], const uint32_t a[4],
                                           const uint32_t b[2]) {
    asm volatile(
        "mma.sync.aligned.m16n8k8.row.col.f32.tf32.tf32.f32 "
        "{%0,%1,%2,%3}, {%4,%5,%6,%7}, {%8,%9}, {%0,%1,%2,%3};"
        : "+f"(c[0]), "+f"(c[1]), "+f"(c[2]), "+f"(c[3])
        : "r"(a[0]), "r"(a[1]), "r"(a[2]), "r"(a[3]), "r"(b[0]), "r"(b[1]));
}

__device__ __forceinline__ float relu_(float v) { return fmaxf(v, 0.0f); }

// streaming (evict-first) 128-bit store
__device__ __forceinline__ void stg_cs_v4(float* p, float a, float b,
                                          float c, float d) {
    asm volatile("st.global.cs.v4.f32 [%0], {%1, %2, %3, %4};"
                 :: "l"(p), "f"(a), "f"(b), "f"(c), "f"(d) : "memory");
}

__global__ __launch_bounds__(NTHREADS, 2)
void speccnn1d_mma_kernel(const float* __restrict__ x,
                          const float* __restrict__ kern,
                          float* __restrict__ out) {
    __shared__ uint32_t xs_hi[XWIN];
    __shared__ uint32_t xs_lo[XWIN];

    const int tid  = threadIdx.x;
    const int lane = tid & 31;
    const int wid  = tid >> 5;
    const int b    = blockIdx.y;
    const int o0   = blockIdx.x * TILE_O;

    // ---- stage x window, pre-split into tf32 hi/lo (once per CTA) ----
    {
        const float* xb = x + (size_t)b * LSEQ;
        #pragma unroll
        for (int i = tid; i < XWIN; i += NTHREADS) {
            int xi = o0 + i;
            float v = (xi < LSEQ) ? __ldg(&xb[xi]) : 0.0f;
            uint32_t h, l;
            split_tf32(v, h, l);
            xs_hi[i] = h;
            xs_lo[i] = l;
        }
    }
    __syncthreads();

    const int fg = wid & 3;                  // f-group: 32 channels
    const int og = wid >> 2;                 // o-group: 128 rows (8 subtiles)
    const int t  = lane & 3;                 // threadID in group
    const int g  = lane >> 2;                // groupID

    // ---- B fragments, 3xTF32 split, sector-contiguous f permutation ----
    // Block nb, fragment n-index n holds logical
    //   f = fg*32 + 16*(nb>>1) + 4*(n>>1) + 2*(nb&1) + (n&1)   (bijective)
    // => thread t's two float4s are f = fg*32+4t.. and fg*32+16+4t..;
    //    quad t=0..3 covers 64B contiguous per STG.128 (full sectors/lines).
    uint32_t Bb[4][2][2], Bs[4][2][2];
    #pragma unroll
    for (int nb = 0; nb < 4; nb++) {
        const int frow = fg * 32 + 16 * (nb >> 1) + 4 * (g >> 1)
                       + 2 * (nb & 1) + (g & 1);
        const float* wr = kern + (size_t)frow * KW;
        #pragma unroll
        for (int k = 0; k < 2; k++) {
            split_tf32(__ldg(&wr[k * 8 + t]),     Bb[nb][k][0], Bs[nb][k][0]);
            split_tf32(__ldg(&wr[k * 8 + t + 4]), Bb[nb][k][1], Bs[nb][k][1]);
        }
    }

    // row-invariant output base for this thread
    float* outb = out + (size_t)b * OUT_LEN * FCH + fg * 32;

    // ---- 8 o-subtiles of 16 per warp ----
    #pragma unroll
    for (int sub = 0; sub < NSUB; sub++) {
        const int obase = og * (16 * NSUB) + sub * 16;   // local o of subtile

        float C[4][4];
        #pragma unroll
        for (int nb = 0; nb < 4; nb++)
            #pragma unroll
            for (int j = 0; j < 4; j++) C[nb][j] = 0.0f;

        #pragma unroll
        for (int k = 0; k < 2; k++) {
            const int base = obase + g;
            const int kc   = k * 8 + t;
            uint32_t Ab[4], Al[4];
            Ab[0] = xs_hi[base + kc];          Al[0] = xs_lo[base + kc];
            Ab[1] = xs_hi[base + 8 + kc];      Al[1] = xs_lo[base + 8 + kc];
            Ab[2] = xs_hi[base + kc + 4];      Al[2] = xs_lo[base + kc + 4];
            Ab[3] = xs_hi[base + 8 + kc + 4];  Al[3] = xs_lo[base + 8 + kc + 4];

            #pragma unroll
            for (int nb = 0; nb < 4; nb++) {
                mma_16n8k8(C[nb], Ab, Bb[nb][k]);   // big * big
                mma_16n8k8(C[nb], Ab, Bs[nb][k]);   // big * small
                mma_16n8k8(C[nb], Al, Bb[nb][k]);   // small * big
            }
        }

        // ---- epilogue: relu + 2x sector-contiguous streaming STG.128 ----
        const int r0 = o0 + obase + g;
        float* orow = outb + (size_t)r0 * FCH;

        if (r0 < OUT_LEN) {
            stg_cs_v4(orow + 4 * t,
                      relu_(C[0][0]), relu_(C[0][1]),
                      relu_(C[1][0]), relu_(C[1][1]));
            stg_cs_v4(orow + 16 + 4 * t,
                      relu_(C[2][0]), relu_(C[2][1]),
                      relu_(C[3][0]), relu_(C[3][1]));
        }
        if (r0 + 8 < OUT_LEN) {
            float* orow2 = orow + (size_t)8 * FCH;
            stg_cs_v4(orow2 + 4 * t,
                      relu_(C[0][2]), relu_(C[0][3]),
                      relu_(C[1][2]), relu_(C[1][3]));
            stg_cs_v4(orow2 + 16 + 4 * t,
                      relu_(C[2][2]), relu_(C[2][3]),
                      relu_(C[3][2]), relu_(C[3][3]));
        }
    }
}

extern "C" void kernel_launch(void* const* d_in, const int* in_sizes, int n_in,
                              void* d_out, int out_size) {
    const float* x    = (const float*)d_in[0];   // (64, 16384) fp32
    const float* kern = (const float*)d_in[1];   // (128, 16)  fp32
    float* out        = (float*)d_out;           // (64, 16369, 128) fp32

    dim3 grid((OUT_LEN + TILE_O - 1) / TILE_O, BATCH);   // (64, 64)
    speccnn1d_mma_kernel<<<grid, NTHREADS>>>(x, kern, out);
}